// round 14
// baseline (speedup 1.0000x reference)
#include <cuda_runtime.h>
#include <cuda_bf16.h>
#include <math.h>

#define BB 4
#define LL 1536
#define DD 768
#define HH 8
#define NPOS 3071   // 2L-1

typedef __nv_bfloat16 bf16;

// ---------------- scratch (static device globals; no allocation) ----------------
__device__ bf16 g_xh[(size_t)BB * LL * DD],      g_xl[(size_t)BB * LL * DD];
__device__ bf16 g_WTh[1792 * 768],               g_WTl[1792 * 768];   // [Qw|Kw|Vw] transposed
__device__ bf16 g_OwTh[768 * 768],               g_OwTl[768 * 768];
__device__ bf16 g_RwTh[512 * 96],                g_RwTl[512 * 96];
__device__ bf16 g_peh[(size_t)NPOS * 96],        g_pel[(size_t)NPOS * 96];
// rK padded: fused kernel prefetches up to row 3103; pad rows stay zero
__device__ bf16 g_rKh[(size_t)3136 * 512],       g_rKl[(size_t)3136 * 512];
__device__ bf16 g_Qh[(size_t)BB * LL * 512],     g_Ql[(size_t)BB * LL * 512];   // Q*0.125 + rwb
__device__ bf16 g_Kh[(size_t)BB * LL * 512],     g_Kl[(size_t)BB * LL * 512];
__device__ bf16 g_Vth[(size_t)32 * 96 * LL],     g_Vtl[(size_t)32 * 96 * LL];   // V^T per (b,h)
__device__ float g_sbd[8 * NPOS];                                              // delta . rK
__device__ bf16 g_ah[(size_t)BB * LL * 768],     g_al[(size_t)BB * LL * 768];   // attn

// ---------------- small helpers ----------------
__device__ __forceinline__ unsigned smaddr(const void* p) {
    return (unsigned)__cvta_generic_to_shared(p);
}
__device__ __forceinline__ void ldsmx4(unsigned* r, unsigned a) {
    asm volatile("ldmatrix.sync.aligned.m8n8.x4.shared.b16 {%0,%1,%2,%3},[%4];\n"
        : "=r"(r[0]), "=r"(r[1]), "=r"(r[2]), "=r"(r[3]) : "r"(a));
}
__device__ __forceinline__ void ldsmx2(unsigned* r, unsigned a) {
    asm volatile("ldmatrix.sync.aligned.m8n8.x2.shared.b16 {%0,%1},[%2];\n"
        : "=r"(r[0]), "=r"(r[1]) : "r"(a));
}
__device__ __forceinline__ void mma16816(float* c, const unsigned* a, const unsigned* b) {
    asm volatile("mma.sync.aligned.m16n8k16.row.col.f32.bf16.bf16.f32 "
        "{%0,%1,%2,%3},{%4,%5,%6,%7},{%8,%9},{%0,%1,%2,%3};\n"
        : "+f"(c[0]), "+f"(c[1]), "+f"(c[2]), "+f"(c[3])
        : "r"(a[0]), "r"(a[1]), "r"(a[2]), "r"(a[3]), "r"(b[0]), "r"(b[1]));
}
__device__ __forceinline__ void f2split(float v, bf16& h, bf16& l) {
    h = __float2bfloat16(v);
    l = __float2bfloat16(v - __bfloat162float(h));
}
__device__ __forceinline__ unsigned packbf(float x, float y) {
    __nv_bfloat162 t;
    t.x = __float2bfloat16(x);
    t.y = __float2bfloat16(y);
    return *(unsigned*)&t;
}
__device__ __forceinline__ float bfhi(float x) {
    return __bfloat162float(__float2bfloat16(x));
}
// B-fragment pair loader: one ldmatrix.x4 delivers two n8k16 B fragments
// (rows row0..row0+16 of a [n][k] tile with pitch 72, k-cols kb..kb+16).
__device__ __forceinline__ void ldsmB4(unsigned* r, const bf16* base, int row0, int kb, int lane) {
    int j = lane >> 3;
    int row = row0 + (j >> 1) * 8 + (lane & 7);
    int col = kb + (j & 1) * 8;
    ldsmx4(r, smaddr(base + row * 72 + col));
}
#define CPA16(dst, src) asm volatile("cp.async.cg.shared.global [%0], [%1], 16;\n" \
    :: "r"(dst), "l"(src))
#define CPA_COMMIT() asm volatile("cp.async.commit_group;\n")
#define CPA_WAIT0()  asm volatile("cp.async.wait_group 0;\n")

// ---------------- positional features ----------------
__device__ __forceinline__ float gamma_pdf(float x, float cm1, float rate, float lognorm) {
    if (x <= 0.0f) return 0.0f;
    return expf(cm1 * logf(x) - rate * x - lognorm);
}

__device__ void pe_body(bf16* __restrict__ peh, bf16* __restrict__ pel, int idx) {
    if (idx >= NPOS) return;
    float p = (float)(idx - (LL - 1));
    float ap = fabsf(p);
    float sg = (p > 0.f) ? 1.f : ((p < 0.f) ? -1.f : 0.f);
    float max_range = log2f((float)LL);
    size_t base = (size_t)idx * 96;
    #pragma unroll 1
    for (int i = 0; i < 16; i++) {
        float hl = exp2f(3.0f + (max_range - 3.0f) * (float)i * (1.0f / 15.0f));
        float fe = exp2f(-ap / hl);
        float cw = exp2f((float)(i + 1)) - 1.0f;
        float fc = (cw > ap) ? 1.0f : 0.0f;
        float k1 = (float)(i + 1);
        float conc = 4.0f * k1 * k1;
        float rate = k1 * (1.0f / 24.0f);
        float lognorm = lgammaf(conc) - conc * logf(rate);
        float cm1 = conc - 1.0f;
        float mode = cm1 / rate;
        float t0 = fminf(fmaxf(floorf(mode), 0.0f), (float)(LL - 1));
        float t1 = fminf(t0 + 1.0f, (float)(LL - 1));
        float mx = fmaxf(gamma_pdf(t0, cm1, rate, lognorm),
                         gamma_pdf(t1, cm1, rate, lognorm)) + 1e-8f;
        float fg = (gamma_pdf(ap, cm1, rate, lognorm) + 1e-8f) / mx;
        float vals[6] = {fe, fc, fg, sg * fe, sg * fc, sg * fg};
        #pragma unroll
        for (int s = 0; s < 6; s++) {
            bf16 h, l; f2split(vals[s], h, l);
            peh[base + s * 16 + i] = h; pel[base + s * 16 + i] = l;
        }
    }
}

__device__ void tconv_body(const float* __restrict__ in, bf16* __restrict__ oh,
                           bf16* __restrict__ ol, int R, int Cn,
                           int bx, int by, int tid, float* ts) {
    int c0 = bx * 32, r0 = by * 32;
    int tx = tid & 31, ty = tid >> 5;
    #pragma unroll
    for (int t = 0; t < 4; t++)
        ts[(ty + t * 8) * 33 + tx] = in[(size_t)(r0 + ty + t * 8) * Cn + c0 + tx];
    __syncthreads();
    #pragma unroll
    for (int t = 0; t < 4; t++) {
        float v = ts[tx * 33 + ty + t * 8];
        size_t o = (size_t)(c0 + ty + t * 8) * R + r0 + tx;
        bf16 h, l; f2split(v, h, l);
        oh[o] = h; ol[o] = l;
    }
}

// ---------------- prep: convx + all weight transposes + pe, one launch ----------------
__global__ __launch_bounds__(256) void prep_kernel(
    const float* __restrict__ x, const float* __restrict__ Qw,
    const float* __restrict__ Kw, const float* __restrict__ Vw,
    const float* __restrict__ outw, const float* __restrict__ relKw,
    bf16* __restrict__ xh, bf16* __restrict__ xl,
    bf16* __restrict__ WTh, bf16* __restrict__ WTl,
    bf16* __restrict__ OwTh, bf16* __restrict__ OwTl,
    bf16* __restrict__ RwTh, bf16* __restrict__ RwTl,
    bf16* __restrict__ peh, bf16* __restrict__ pel)
{
    __shared__ float ts[32 * 33];
    int b0 = blockIdx.x, tid = threadIdx.x;
    if (b0 < 4608) {
        int idx4 = b0 * 256 + tid;
        float4 v = ((const float4*)x)[idx4];
        bf16 h0, l0, h1, l1, h2, l2, h3, l3;
        f2split(v.x, h0, l0); f2split(v.y, h1, l1);
        f2split(v.z, h2, l2); f2split(v.w, h3, l3);
        __nv_bfloat162 hh0; hh0.x = h0; hh0.y = h1;
        __nv_bfloat162 hh1; hh1.x = h2; hh1.y = h3;
        __nv_bfloat162 ll0; ll0.x = l0; ll0.y = l1;
        __nv_bfloat162 ll1; ll1.x = l2; ll1.y = l3;
        ((__nv_bfloat162*)xh)[idx4 * 2]     = hh0;
        ((__nv_bfloat162*)xh)[idx4 * 2 + 1] = hh1;
        ((__nv_bfloat162*)xl)[idx4 * 2]     = ll0;
        ((__nv_bfloat162*)xl)[idx4 * 2 + 1] = ll1;
    } else if (b0 < 4992) {
        int l = b0 - 4608;
        tconv_body(Qw, WTh, WTl, 768, 512, l % 16, l / 16, tid, ts);
    } else if (b0 < 5376) {
        int l = b0 - 4992;
        tconv_body(Kw, WTh + (size_t)512 * 768, WTl + (size_t)512 * 768,
                   768, 512, l % 16, l / 16, tid, ts);
    } else if (b0 < 5952) {
        int l = b0 - 5376;
        tconv_body(Vw, WTh + (size_t)1024 * 768, WTl + (size_t)1024 * 768,
                   768, 768, l % 24, l / 24, tid, ts);
    } else if (b0 < 6528) {
        int l = b0 - 5952;
        tconv_body(outw, OwTh, OwTl, 768, 768, l % 24, l / 24, tid, ts);
    } else if (b0 < 6576) {
        int l = b0 - 6528;
        tconv_body(relKw, RwTh, RwTl, 96, 512, l % 16, l / 16, tid, ts);
    } else {
        pe_body(peh, pel, (b0 - 6576) * 256 + tid);
    }
}

// ---------------- old-style split-bf16 GEMM (used for rK only) ----------------
template<int BN>
__global__ __launch_bounds__(256) void hgemm(
    const bf16* __restrict__ Ah, const bf16* __restrict__ Al, int lda,
    const bf16* __restrict__ Bh, const bf16* __restrict__ Bl, int ldb,
    bf16* __restrict__ Ch, bf16* __restrict__ Cl, int ldc,
    int M, int K)
{
    constexpr int PAD = 40;
    constexpr int NT = BN / 16;
    __shared__ __align__(16) bf16 sAh[128 * PAD], sAl[128 * PAD];
    __shared__ __align__(16) bf16 sBh[BN * PAD],  sBl[BN * PAD];

    int i0 = blockIdx.y * 128, j0 = blockIdx.x * BN;
    int tid = threadIdx.x, warp = tid >> 5, lane = tid & 31;
    int wm = warp >> 1, wn = warp & 1;
    int m0 = wm * 32, n0 = wn * (BN / 2);

    float acc[2][NT][4] = {};

    for (int kk = 0; kk < K; kk += 32) {
        uint4 avh[2], avl[2], bvh, bvl;
        #pragma unroll
        for (int t = 0; t < 2; t++) {
            int idx = tid + t * 256;
            int row = idx >> 2, c16 = idx & 3;
            int gr = i0 + row;
            if (gr < M) {
                avh[t] = *(const uint4*)(Ah + (size_t)gr * lda + kk + c16 * 8);
                avl[t] = *(const uint4*)(Al + (size_t)gr * lda + kk + c16 * 8);
            } else {
                avh[t] = make_uint4(0, 0, 0, 0); avl[t] = make_uint4(0, 0, 0, 0);
            }
        }
        {
            int row = tid >> 2, c16 = tid & 3;
            bvh = *(const uint4*)(Bh + (size_t)(j0 + row) * ldb + kk + c16 * 8);
            bvl = *(const uint4*)(Bl + (size_t)(j0 + row) * ldb + kk + c16 * 8);
        }
        __syncthreads();
        #pragma unroll
        for (int t = 0; t < 2; t++) {
            int idx = tid + t * 256;
            int row = idx >> 2, c16 = idx & 3;
            *(uint4*)(sAh + row * PAD + c16 * 8) = avh[t];
            *(uint4*)(sAl + row * PAD + c16 * 8) = avl[t];
        }
        {
            int row = tid >> 2, c16 = tid & 3;
            *(uint4*)(sBh + row * PAD + c16 * 8) = bvh;
            *(uint4*)(sBl + row * PAD + c16 * 8) = bvl;
        }
        __syncthreads();
        #pragma unroll
        for (int ks = 0; ks < 2; ks++) {
            int kb = ks * 16;
            unsigned ah[2][4], al[2][4], bh[NT][2], bl[NT][2];
            #pragma unroll
            for (int mt = 0; mt < 2; mt++) {
                int arow = m0 + mt * 16 + (lane & 15);
                int acol = kb + (lane >> 4) * 8;
                ldsmx4(ah[mt], smaddr(sAh + arow * PAD + acol));
                ldsmx4(al[mt], smaddr(sAl + arow * PAD + acol));
            }
            #pragma unroll
            for (int nt = 0; nt < NT; nt++) {
                int brow = n0 + nt * 8 + (lane & 7);
                int bcol = kb + ((lane >> 3) & 1) * 8;
                ldsmx2(bh[nt], smaddr(sBh + brow * PAD + bcol));
                ldsmx2(bl[nt], smaddr(sBl + brow * PAD + bcol));
            }
            #pragma unroll
            for (int mt = 0; mt < 2; mt++)
                #pragma unroll
                for (int nt = 0; nt < NT; nt++) {
                    mma16816(acc[mt][nt], ah[mt], bh[nt]);
                    mma16816(acc[mt][nt], ah[mt], bl[nt]);
                    mma16816(acc[mt][nt], al[mt], bh[nt]);
                }
        }
        __syncthreads();
    }

    #pragma unroll
    for (int mt = 0; mt < 2; mt++)
        #pragma unroll
        for (int nt = 0; nt < NT; nt++) {
            int r0 = i0 + m0 + mt * 16 + (lane >> 2);
            int jn = j0 + n0 + nt * 8 + ((lane & 3) << 1);
            float v00 = acc[mt][nt][0], v01 = acc[mt][nt][1];
            float v10 = acc[mt][nt][2], v11 = acc[mt][nt][3];
            bf16 h0, l0, h1, l1;
            if (r0 < M) {
                f2split(v00, h0, l0); f2split(v01, h1, l1);
                __nv_bfloat162 hh; hh.x = h0; hh.y = h1;
                __nv_bfloat162 ll; ll.x = l0; ll.y = l1;
                *(__nv_bfloat162*)(Ch + (size_t)r0 * ldc + jn) = hh;
                *(__nv_bfloat162*)(Cl + (size_t)r0 * ldc + jn) = ll;
            }
            if (r0 + 8 < M) {
                f2split(v10, h0, l0); f2split(v11, h1, l1);
                __nv_bfloat162 hh; hh.x = h0; hh.y = h1;
                __nv_bfloat162 ll; ll.x = l0; ll.y = l1;
                *(__nv_bfloat162*)(Ch + (size_t)(r0 + 8) * ldc + jn) = hh;
                *(__nv_bfloat162*)(Cl + (size_t)(r0 + 8) * ldc + jn) = ll;
            }
        }
}

// ======= improved 128x128 GEMM core: warp tile 64x32 =======
struct G128Acc { float a[4][4][4]; };

__device__ __forceinline__ void gemm128_core(
    const bf16* __restrict__ Ah, const bf16* __restrict__ Al, int lda,
    const bf16* __restrict__ Bh, const bf16* __restrict__ Bl, int ldb,
    int i0, int j0, int K, G128Acc& A_,
    bf16* sAh, bf16* sAl, bf16* sBh, bf16* sBl)
{
    constexpr int PAD = 40;
    int tid = threadIdx.x, warp = tid >> 5, lane = tid & 31;
    int m0 = (warp >> 2) * 64, n0 = (warp & 3) * 32;

    for (int kk = 0; kk < K; kk += 32) {
        uint4 avh[2], avl[2], bvh[2], bvl[2];
        #pragma unroll
        for (int t = 0; t < 2; t++) {
            int idx = tid + t * 256;
            int row = idx >> 2, c16 = idx & 3;
            avh[t] = *(const uint4*)(Ah + (size_t)(i0 + row) * lda + kk + c16 * 8);
            avl[t] = *(const uint4*)(Al + (size_t)(i0 + row) * lda + kk + c16 * 8);
            bvh[t] = *(const uint4*)(Bh + (size_t)(j0 + row) * ldb + kk + c16 * 8);
            bvl[t] = *(const uint4*)(Bl + (size_t)(j0 + row) * ldb + kk + c16 * 8);
        }
        __syncthreads();
        #pragma unroll
        for (int t = 0; t < 2; t++) {
            int idx = tid + t * 256;
            int row = idx >> 2, c16 = idx & 3;
            *(uint4*)(sAh + row * PAD + c16 * 8) = avh[t];
            *(uint4*)(sAl + row * PAD + c16 * 8) = avl[t];
            *(uint4*)(sBh + row * PAD + c16 * 8) = bvh[t];
            *(uint4*)(sBl + row * PAD + c16 * 8) = bvl[t];
        }
        __syncthreads();
        #pragma unroll
        for (int ks = 0; ks < 2; ks++) {
            int kb = ks * 16;
            unsigned ah[4][4], al[4][4], bh[4][2], bl[4][2];
            #pragma unroll
            for (int mt = 0; mt < 4; mt++) {
                int arow = m0 + mt * 16 + (lane & 15);
                int acol = kb + (lane >> 4) * 8;
                ldsmx4(ah[mt], smaddr(sAh + arow * PAD + acol));
                ldsmx4(al[mt], smaddr(sAl + arow * PAD + acol));
            }
            #pragma unroll
            for (int nt = 0; nt < 4; nt++) {
                int brow = n0 + nt * 8 + (lane & 7);
                int bcol = kb + ((lane >> 3) & 1) * 8;
                ldsmx2(bh[nt], smaddr(sBh + brow * PAD + bcol));
                ldsmx2(bl[nt], smaddr(sBl + brow * PAD + bcol));
            }
            #pragma unroll
            for (int mt = 0; mt < 4; mt++)
                #pragma unroll
                for (int nt = 0; nt < 4; nt++) {
                    mma16816(A_.a[mt][nt], ah[mt], bh[nt]);
                    mma16816(A_.a[mt][nt], ah[mt], bl[nt]);
                    mma16816(A_.a[mt][nt], al[mt], bh[nt]);
                }
        }
        __syncthreads();
    }
}

// ---------------- out projection: fp32 out + bias ----------------
__global__ __launch_bounds__(256) void out_gemm(
    const bf16* __restrict__ Ah, const bf16* __restrict__ Al,
    const bf16* __restrict__ Bh, const bf16* __restrict__ Bl,
    float* __restrict__ Cf, const float* __restrict__ bias)
{
    constexpr int PAD = 40;
    __shared__ __align__(16) bf16 sAh[128 * PAD], sAl[128 * PAD];
    __shared__ __align__(16) bf16 sBh[128 * PAD], sBl[128 * PAD];
    int i0 = blockIdx.y * 128, j0 = blockIdx.x * 128;
    int warp = threadIdx.x >> 5, lane = threadIdx.x & 31;
    int m0 = (warp >> 2) * 64, n0 = (warp & 3) * 32;

    G128Acc acc;
    #pragma unroll
    for (int mt = 0; mt < 4; mt++)
        #pragma unroll
        for (int nt = 0; nt < 4; nt++)
            #pragma unroll
            for (int e = 0; e < 4; e++) acc.a[mt][nt][e] = 0.0f;

    gemm128_core(Ah, Al, 768, Bh, Bl, 768, i0, j0, 768, acc, sAh, sAl, sBh, sBl);

    #pragma unroll
    for (int mt = 0; mt < 4; mt++)
        #pragma unroll
        for (int nt = 0; nt < 4; nt++) {
            int r0 = i0 + m0 + mt * 16 + (lane >> 2);
            int jn = j0 + n0 + nt * 8 + ((lane & 3) << 1);
            float b0 = bias[jn], b1 = bias[jn + 1];
            *(float2*)(Cf + (size_t)r0 * 768 + jn) =
                make_float2(acc.a[mt][nt][0] + b0, acc.a[mt][nt][1] + b1);
            *(float2*)(Cf + (size_t)(r0 + 8) * 768 + jn) =
                make_float2(acc.a[mt][nt][2] + b0, acc.a[mt][nt][3] + b1);
        }
}

// ---------------- merged QKV projection + V-transpose epilogue + sbd blocks ----------------
__global__ __launch_bounds__(256) void qkv_gemm(
    const bf16* __restrict__ Ah, const bf16* __restrict__ Al,
    const bf16* __restrict__ Bh, const bf16* __restrict__ Bl,
    bf16* __restrict__ Qh, bf16* __restrict__ Ql,
    bf16* __restrict__ Kh, bf16* __restrict__ Kl,
    bf16* __restrict__ Vth, bf16* __restrict__ Vtl,
    const float* __restrict__ rwb,
    const bf16* __restrict__ Rh, const bf16* __restrict__ Rl,
    const float* __restrict__ rrb, float* __restrict__ sbd)
{
    constexpr int PAD = 40;
    __shared__ __align__(16) bf16 sAh[128 * PAD], sAl[128 * PAD];
    __shared__ __align__(16) bf16 sBh[128 * PAD], sBl[128 * PAD];
    int tid = threadIdx.x;

    if (blockIdx.x == 14) {
        int idx0 = blockIdx.y * 256 + tid;
        #pragma unroll
        for (int rep = 0; rep < 2; rep++) {
            int idx = idx0 + rep * 12288;
            if (idx < 8 * NPOS) {
                int h = idx / NPOS, p = idx % NPOS;
                float s = 0.0f;
                #pragma unroll 8
                for (int d = 0; d < 64; d++) {
                    size_t o = (size_t)p * 512 + h * 64 + d;
                    s += (rrb[h * 64 + d] - rwb[h * 64 + d]) *
                         (__bfloat162float(Rh[o]) + __bfloat162float(Rl[o]));
                }
                sbd[idx] = s;
            }
        }
        return;
    }

    int i0 = blockIdx.y * 128, j0 = blockIdx.x * 128;
    int warp = tid >> 5, lane = tid & 31;
    int m0 = (warp >> 2) * 64, n0 = (warp & 3) * 32;

    G128Acc acc;
    #pragma unroll
    for (int mt = 0; mt < 4; mt++)
        #pragma unroll
        for (int nt = 0; nt < 4; nt++)
            #pragma unroll
            for (int e = 0; e < 4; e++) acc.a[mt][nt][e] = 0.0f;

    gemm128_core(Ah, Al, 768, Bh, Bl, 768, i0, j0, 768, acc, sAh, sAl, sBh, sBl);

    int jt = blockIdx.x;
    if (jt < 8) {
        bf16 *Ch, *Cl; int jbase; float alpha; const float* bias;
        if (jt < 4) { Ch = Qh; Cl = Ql; jbase = jt * 128; alpha = 0.125f; bias = rwb; }
        else        { Ch = Kh; Cl = Kl; jbase = (jt - 4) * 128; alpha = 1.0f; bias = nullptr; }
        #pragma unroll
        for (int mt = 0; mt < 4; mt++)
            #pragma unroll
            for (int nt = 0; nt < 4; nt++) {
                int r0 = i0 + m0 + mt * 16 + (lane >> 2);
                int jn = jbase + n0 + nt * 8 + ((lane & 3) << 1);
                float b0 = bias ? bias[jn] : 0.0f;
                float b1 = bias ? bias[jn + 1] : 0.0f;
                float v00 = alpha * acc.a[mt][nt][0] + b0;
                float v01 = alpha * acc.a[mt][nt][1] + b1;
                float v10 = alpha * acc.a[mt][nt][2] + b0;
                float v11 = alpha * acc.a[mt][nt][3] + b1;
                bf16 h0, l0, h1, l1;
                f2split(v00, h0, l0); f2split(v01, h1, l1);
                __nv_bfloat162 hh; hh.x = h0; hh.y = h1;
                __nv_bfloat162 ll; ll.x = l0; ll.y = l1;
                *(__nv_bfloat162*)(Ch + (size_t)r0 * 512 + jn) = hh;
                *(__nv_bfloat162*)(Cl + (size_t)r0 * 512 + jn) = ll;
                f2split(v10, h0, l0); f2split(v11, h1, l1);
                hh.x = h0; hh.y = h1; ll.x = l0; ll.y = l1;
                *(__nv_bfloat162*)(Ch + (size_t)(r0 + 8) * 512 + jn) = hh;
                *(__nv_bfloat162*)(Cl + (size_t)(r0 + 8) * 512 + jn) = ll;
            }
    } else {
        #pragma unroll
        for (int mt = 0; mt < 4; mt++)
            #pragma unroll
            for (int nt = 0; nt < 4; nt++) {
                int r = i0 + m0 + mt * 16 + (lane >> 2);
                int cv = (jt - 8) * 128 + n0 + nt * 8 + ((lane & 3) << 1);
                int bb2 = r / LL;
                int ii = r - bb2 * LL;
                int h = cv / 96, dv = cv - h * 96;
                size_t zo = ((size_t)(bb2 * 8 + h)) * 96 * LL;
                bf16 h0, l0;
                f2split(acc.a[mt][nt][0], h0, l0);
                Vth[zo + (size_t)dv * LL + ii] = h0;
                Vtl[zo + (size_t)dv * LL + ii] = l0;
                f2split(acc.a[mt][nt][1], h0, l0);
                Vth[zo + (size_t)(dv + 1) * LL + ii] = h0;
                Vtl[zo + (size_t)(dv + 1) * LL + ii] = l0;
                f2split(acc.a[mt][nt][2], h0, l0);
                Vth[zo + (size_t)dv * LL + ii + 8] = h0;
                Vtl[zo + (size_t)dv * LL + ii + 8] = l0;
                f2split(acc.a[mt][nt][3], h0, l0);
                Vth[zo + (size_t)(dv + 1) * LL + ii + 8] = h0;
                Vtl[zo + (size_t)(dv + 1) * LL + ii + 8] = l0;
            }
    }
}

// ========= fused flash attention: i-tile 64, single-buffered, 2 CTAs/SM =========
// smem (98,304 B): K 18,432 | band 18,432 | V 27,648 | bandS 33,280 (Q aliased) | sbd 512
#define OFF_K    0
#define OFF_BND  18432
#define OFF_V    36864
#define OFF_BS   64512
#define OFF_SBD  97792
#define FA_SMEM  98304

__global__ void __launch_bounds__(256, 2) fused_attn(
    const bf16* __restrict__ Qh, const bf16* __restrict__ Ql,
    const bf16* __restrict__ Kh, const bf16* __restrict__ Kl,
    const bf16* __restrict__ Rh, const bf16* __restrict__ Rl,
    const bf16* __restrict__ Vth, const bf16* __restrict__ Vtl,
    const float* __restrict__ sbd_g,
    bf16* __restrict__ Oh, bf16* __restrict__ Ol)
{
    extern __shared__ __align__(16) unsigned char smc[];
    bf16* sKh = (bf16*)(smc + OFF_K);
    bf16* sKl = (bf16*)(smc + OFF_K + 9216);
    bf16* sBh = (bf16*)(smc + OFF_BND);
    bf16* sBl = (bf16*)(smc + OFF_BND + 9216);
    bf16* sVh = (bf16*)(smc + OFF_V);
    bf16* sVl = (bf16*)(smc + OFF_V + 13824);
    float* bandS = (float*)(smc + OFF_BS);          // 64 x 130 fp32
    bf16* sQh = (bf16*)(smc + OFF_BS);              // aliased (prologue only)
    bf16* sQl = (bf16*)(smc + OFF_BS + 9216);
    float* sbdS = (float*)(smc + OFF_SBD);          // 127 floats

    int tid = threadIdx.x, warp = tid >> 5, lane = tid & 31;
    int wm = warp >> 1, wn = warp & 1;
    int m0 = wm * 16;
    int z = blockIdx.y, b = z >> 3, h = z & 7;
    int i0 = blockIdx.x * 64;
    size_t qkbase = ((size_t)b * LL) * 512 + h * 64;
    size_t voff = (size_t)z * 96 * LL;
    int bandbase = 1472 - i0;                       // >= 0

    // ---- prologue group1: Q (aliased in bandS) + band seg0 (band slot) ----
    #pragma unroll
    for (int t = 0; t < 4; t++) {
        int idx = tid + t * 256;
        int sp = idx >> 9;
        int r = (idx & 511) >> 3, c16 = idx & 7;
        CPA16(smaddr((sp ? sQl : sQh) + r * 72 + c16 * 8),
              (sp ? Ql : Qh) + qkbase + (size_t)(i0 + r) * 512 + c16 * 8);
        CPA16(smaddr((sp ? sBl : sBh) + r * 72 + c16 * 8),
              (sp ? Rl : Rh) + (size_t)(bandbase + r) * 512 + h * 64 + c16 * 8);
    }
    CPA_COMMIT();
    CPA_WAIT0();
    __syncthreads();

    unsigned aQh[4][4], aQl[4][4];
    #pragma unroll
    for (int ks = 0; ks < 4; ks++) {
        int arow = m0 + (lane & 15);
        int acol = ks * 16 + (lane >> 4) * 8;
        ldsmx4(aQh[ks], smaddr(sQh + arow * 72 + acol));
        ldsmx4(aQl[ks], smaddr(sQl + arow * 72 + acol));
    }
    int r4 = lane >> 2, c2 = (lane & 3) << 1;
    int rowA = m0 + r4, rowB = rowA + 8;

    // band seg0 mma (rows m0..+16, band cols wn*32..+32)
    float bacc0[4][4] = {};
    #pragma unroll
    for (int ks = 0; ks < 4; ks++) {
        #pragma unroll
        for (int p = 0; p < 2; p++) {
            unsigned bh4[4], bl4[4];
            ldsmB4(bh4, sBh, wn * 32 + p * 16, ks * 16, lane);
            ldsmB4(bl4, sBl, wn * 32 + p * 16, ks * 16, lane);
            mma16816(bacc0[p * 2], aQh[ks], bh4);
            mma16816(bacc0[p * 2], aQh[ks], bl4);
            mma16816(bacc0[p * 2], aQl[ks], bh4);
            mma16816(bacc0[p * 2 + 1], aQh[ks], bh4 + 2);
            mma16816(bacc0[p * 2 + 1], aQh[ks], bl4 + 2);
            mma16816(bacc0[p * 2 + 1], aQl[ks], bh4 + 2);
        }
    }
    __syncthreads();     // all Q reads done before bandS (alias) writes
    #pragma unroll
    for (int nt = 0; nt < 4; nt++) {
        int col = wn * 32 + nt * 8 + c2;            // phys slot 0
        bandS[rowA * 130 + col]     = bacc0[nt][0];
        bandS[rowA * 130 + col + 1] = bacc0[nt][1];
        bandS[rowB * 130 + col]     = bacc0[nt][2];
        bandS[rowB * 130 + col + 1] = bacc0[nt][3];
    }
    // ---- prologue group2: K(0), band seg1, V(0) ----
    #pragma unroll
    for (int t = 0; t < 4; t++) {
        int idx = tid + t * 256;
        int sp = idx >> 9;
        int r = (idx & 511) >> 3, c16 = idx & 7;
        CPA16(smaddr((sp ? sKl : sKh) + r * 72 + c16 * 8),
              (sp ? Kl : Kh) + qkbase + (size_t)r * 512 + c16 * 8);
        CPA16(smaddr((sp ? sBl : sBh) + r * 72 + c16 * 8),
              (sp ? Rl : Rh) + (size_t)(bandbase + 64 + r) * 512 + h * 64 + c16 * 8);
    }
    #pragma unroll
    for (int t = 0; t < 6; t++) {
        int idx = tid + t * 256;
        int sp = idx >= 768;
        int rem = idx - sp * 768;
        int r = rem >> 3, c16 = rem & 7;
        CPA16(smaddr((sp ? sVl : sVh) + r * 72 + c16 * 8),
              (sp ? Vtl : Vth) + voff + (size_t)r * LL + c16 * 8);
    }
    CPA_COMMIT();

    float mA = -1e30f, mB = -1e30f, lA = 0.0f, lB = 0.0f;
    float acc[12][4];
    #pragma unroll
    for (int n = 0; n < 12; n++)
        #pragma unroll
        for (int e = 0; e < 4; e++) acc[n][e] = 0.0f;

    for (int jt = 0; jt < 24; jt++) {
        int j0 = jt * 64;
        int k0g = 1472 + j0 - i0;
        float sbdv = (tid < 127) ? sbd_g[h * NPOS + k0g + tid] : 0.0f;

        CPA_WAIT0();
        __syncthreads();   // [A] K(jt), band seg jt+1, V(jt) ready; prev iter fully done

        // band seg jt+1 mma + content mma (consume band, K)
        float bacc[4][4] = {};
        float cacc[4][4] = {};
        #pragma unroll
        for (int ks = 0; ks < 4; ks++) {
            #pragma unroll
            for (int p = 0; p < 2; p++) {
                unsigned bh4[4], bl4[4];
                ldsmB4(bh4, sBh, wn * 32 + p * 16, ks * 16, lane);
                ldsmB4(bl4, sBl, wn * 32 + p * 16, ks * 16, lane);
                mma16816(bacc[p * 2], aQh[ks], bh4);
                mma16816(bacc[p * 2], aQh[ks], bl4);
                mma16816(bacc[p * 2], aQl[ks], bh4);
                mma16816(bacc[p * 2 + 1], aQh[ks], bh4 + 2);
                mma16816(bacc[p * 2 + 1], aQh[ks], bl4 + 2);
                mma16816(bacc[p * 2 + 1], aQl[ks], bh4 + 2);
                unsigned kh4[4], kl4[4];
                ldsmB4(kh4, sKh, wn * 32 + p * 16, ks * 16, lane);
                ldsmB4(kl4, sKl, wn * 32 + p * 16, ks * 16, lane);
                mma16816(cacc[p * 2], aQh[ks], kh4);
                mma16816(cacc[p * 2], aQh[ks], kl4);
                mma16816(cacc[p * 2], aQl[ks], kh4);
                mma16816(cacc[p * 2 + 1], aQh[ks], kh4 + 2);
                mma16816(cacc[p * 2 + 1], aQh[ks], kl4 + 2);
                mma16816(cacc[p * 2 + 1], aQl[ks], kh4 + 2);
            }
        }
        {
            int phys = (jt + 1) & 1;
            #pragma unroll
            for (int nt = 0; nt < 4; nt++) {
                int col = phys * 64 + wn * 32 + nt * 8 + c2;
                bandS[rowA * 130 + col]     = bacc[nt][0];
                bandS[rowA * 130 + col + 1] = bacc[nt][1];
                bandS[rowB * 130 + col]     = bacc[nt][2];
                bandS[rowB * 130 + col + 1] = bacc[nt][3];
            }
        }
        if (tid < 127) sbdS[tid] = sbdv;
        __syncthreads();   // [B] K/band consumed; bandS + sbdS visible

        // issue K(jt+1) + band seg jt+2 — overlaps softmax + PV below
        if (jt + 1 < 24) {
            #pragma unroll
            for (int t = 0; t < 4; t++) {
                int idx = tid + t * 256;
                int sp = idx >> 9;
                int r = (idx & 511) >> 3, c16 = idx & 7;
                CPA16(smaddr((sp ? sKl : sKh) + r * 72 + c16 * 8),
                      (sp ? Kl : Kh) + qkbase + (size_t)(j0 + 64 + r) * 512 + c16 * 8);
                CPA16(smaddr((sp ? sBl : sBh) + r * 72 + c16 * 8),
                      (sp ? Rl : Rh) + (size_t)(bandbase + 64 * (jt + 2) + r) * 512 + h * 64 + c16 * 8);
            }
            CPA_COMMIT();
        }

        // assembly + softmax
        float rmA = -1e30f, rmB = -1e30f;
        #pragma unroll
        for (int nt = 0; nt < 4; nt++) {
            int jj0 = wn * 32 + nt * 8 + c2;
            #pragma unroll
            for (int u = 0; u < 2; u++) {
                int jj = jj0 + u;
                int pA = 63 + jj - rowA;            // [0, 126]
                int pB = 63 + jj - rowB;
                int iA = ((jt + (pA >> 6)) & 1) * 64 + (pA & 63);
                int iB = ((jt + (pB >> 6)) & 1) * 64 + (pB & 63);
                cacc[nt][u]     += bandS[rowA * 130 + iA] + sbdS[pA];
                cacc[nt][2 + u] += bandS[rowB * 130 + iB] + sbdS[pB];
                rmA = fmaxf(rmA, cacc[nt][u]);
                rmB = fmaxf(rmB, cacc[nt][2 + u]);
            }
        }
        rmA = fmaxf(rmA, __shfl_xor_sync(0xffffffffu, rmA, 1));
        rmA = fmaxf(rmA, __shfl_xor_sync(0xffffffffu, rmA, 2));
        rmB = fmaxf(rmB, __shfl_xor_sync(0xffffffffu, rmB, 1));
        rmB = fmaxf(rmB, __shfl_xor_sync(0xffffffffu, rmB, 2));

        float mnA = fmaxf(mA, rmA), mnB = fmaxf(mB, rmB);
        float alA = __expf(mA - mnA), alB = __expf(mB - mnB);
        mA = mnA; mB = mnB;

        float ssA = 0.0f, ssB = 0.0f;
        #pragma unroll
        for (int nt = 0; nt < 4; nt++) {
            cacc[nt][0] = __expf(cacc[nt][0] - mA);
            cacc[nt][1] = __expf(cacc[nt][1] - mA);
            cacc[nt][2] = __expf(cacc[nt][2] - mB);
            cacc[nt][3] = __expf(cacc[nt][3] - mB);
            ssA += cacc[nt][0] + cacc[nt][1];
            ssB += cacc[nt][2] + cacc[nt][3];
        }
        ssA += __shfl_xor_sync(0xffffffffu, ssA, 1);
        ssA += __shfl_xor_sync(0xffffffffu, ssA, 2);
        ssB += __shfl_xor_sync(0xffffffffu, ssB, 1);
        ssB += __shfl_xor_sync(0xffffffffu, ssB, 2);
        lA = lA * alA + ssA;
        lB = lB * alB + ssB;
        #pragma unroll
        for (int n = 0; n < 12; n++) {
            acc[n][0] *= alA; acc[n][1] *= alA;
            acc[n][2] *= alB; acc[n][3] *= alB;
        }

        // PV: P (k = wn*32..+32) x V (consume V)
        #pragma unroll
        for (int ks = 0; ks < 2; ks++) {
            int n2 = ks * 2;
            unsigned aPh[4], aPl[4];
            aPh[0] = packbf(cacc[n2][0], cacc[n2][1]);
            aPh[1] = packbf(cacc[n2][2], cacc[n2][3]);
            aPh[2] = packbf(cacc[n2 + 1][0], cacc[n2 + 1][1]);
            aPh[3] = packbf(cacc[n2 + 1][2], cacc[n2 + 1][3]);
            aPl[0] = packbf(cacc[n2][0] - bfhi(cacc[n2][0]), cacc[n2][1] - bfhi(cacc[n2][1]));
            aPl[1] = packbf(cacc[n2][2] - bfhi(cacc[n2][2]), cacc[n2][3] - bfhi(cacc[n2][3]));
            aPl[2] = packbf(cacc[n2 + 1][0] - bfhi(cacc[n2 + 1][0]), cacc[n2 + 1][1] - bfhi(cacc[n2 + 1][1]));
            aPl[3] = packbf(cacc[n2 + 1][2] - bfhi(cacc[n2 + 1][2]), cacc[n2 + 1][3] - bfhi(cacc[n2 + 1][3]));
            int vcol = wn * 32 + ks * 16;
            #pragma unroll
            for (int pp = 0; pp < 6; pp++) {
                unsigned vh4[4], vl4[4];
                ldsmB4(vh4, sVh, pp * 16, vcol, lane);
                ldsmB4(vl4, sVl, pp * 16, vcol, lane);
                mma16816(acc[2 * pp], aPh, vh4);
                mma16816(acc[2 * pp], aPh, vl4);
                mma16816(acc[2 * pp], aPl, vh4);
                mma16816(acc[2 * pp + 1], aPh, vh4 + 2);
                mma16816(acc[2 * pp + 1], aPh, vl4 + 2);
                mma16816(acc[2 * pp + 1], aPl, vh4 + 2);
            }
        }
        __syncthreads();   // [C] V consumed by all warps

        if (jt + 1 < 24) {
            #pragma unroll
            for (int t = 0; t < 6; t++) {
                int idx = tid + t * 256;
                int sp = idx >= 768;
                int rem = idx - sp * 768;
                int r = rem >> 3, c16 = rem & 7;
                CPA16(smaddr((sp ? sVl : sVh) + r * 72 + c16 * 8),
                      (sp ? Vtl : Vth) + voff + (size_t)r * LL + j0 + 64 + c16 * 8);
            }
            CPA_COMMIT();
        }
    }

    // ---- epilogue: merge the two wn halves, divide, write split bf16 ----
    __syncthreads();
    float* exch = bandS;
    float* mS = bandS + 6144;
    float* lS = bandS + 6208;
    if (wn == 1) {
        #pragma unroll
        for (int nt = 0; nt < 12; nt++) {
            int col = nt * 8 + c2;
            exch[rowA * 96 + col]     = acc[nt][0];
            exch[rowA * 96 + col + 1] = acc[nt][1];
            exch[rowB * 96 + col]     = acc[nt][2];
            exch[rowB * 96 + col + 1] = acc[nt][3];
        }
        if ((lane & 3) == 0) {
            mS[rowA] = mA; lS[rowA] = lA;
            mS[rowB] = mB; lS[rowB] = lB;
        }
    }
    __syncthreads();
    if (wn == 0) {
        float m1A = mS[rowA], l1A = lS[rowA];
        float m1B = mS[rowB], l1B = lS[rowB];
        float mMA = fmaxf(mA, m1A), mMB = fmaxf(mB, m1B);
        float c0A = __expf(mA - mMA), c1A = __expf(m1A - mMA);
        float c0B = __expf(mB - mMB), c1B = __expf(m1B - mMB);
        float invA = 1.0f / (c0A * lA + c1A * l1A);
        float invB = 1.0f / (c0B * lB + c1B * l1B);
        size_t obase = ((size_t)(b * LL + i0)) * 768 + h * 96;
        #pragma unroll
        for (int nt = 0; nt < 12; nt++) {
            int col = nt * 8 + c2;
            float d0 = (c0A * acc[nt][0] + c1A * exch[rowA * 96 + col]) * invA;
            float d1 = (c0A * acc[nt][1] + c1A * exch[rowA * 96 + col + 1]) * invA;
            float d2 = (c0B * acc[nt][2] + c1B * exch[rowB * 96 + col]) * invB;
            float d3 = (c0B * acc[nt][3] + c1B * exch[rowB * 96 + col + 1]) * invB;
            bf16 h0, l0, h1, l1;
            f2split(d0, h0, l0); f2split(d1, h1, l1);
            __nv_bfloat162 hh; hh.x = h0; hh.y = h1;
            __nv_bfloat162 ll; ll.x = l0; ll.y = l1;
            *(__nv_bfloat162*)(Oh + obase + (size_t)rowA * 768 + col) = hh;
            *(__nv_bfloat162*)(Ol + obase + (size_t)rowA * 768 + col) = ll;
            f2split(d2, h0, l0); f2split(d3, h1, l1);
            hh.x = h0; hh.y = h1; ll.x = l0; ll.y = l1;
            *(__nv_bfloat162*)(Oh + obase + (size_t)rowB * 768 + col) = hh;
            *(__nv_bfloat162*)(Ol + obase + (size_t)rowB * 768 + col) = ll;
        }
    }
}

// ---------------- launch ----------------
extern "C" void kernel_launch(void* const* d_in, const int* in_sizes, int n_in,
                              void* d_out, int out_size) {
    (void)in_sizes; (void)n_in; (void)out_size;
    const float* x     = (const float*)d_in[0];
    const float* Qw    = (const float*)d_in[1];
    const float* Kw    = (const float*)d_in[2];
    const float* Vw    = (const float*)d_in[3];
    const float* outw  = (const float*)d_in[4];
    const float* outb  = (const float*)d_in[5];
    const float* relKw = (const float*)d_in[6];
    const float* rwb   = (const float*)d_in[7];
    const float* rrb   = (const float*)d_in[8];

    bf16 *xh, *xl, *WTh, *WTl, *OwTh, *OwTl, *RwTh, *RwTl;
    bf16 *peh, *pel, *rKh, *rKl, *Qh, *Ql, *Kh, *Kl, *Vth, *Vtl, *ath, *atl;
    float *sbd;
    cudaGetSymbolAddress((void**)&xh, g_xh);     cudaGetSymbolAddress((void**)&xl, g_xl);
    cudaGetSymbolAddress((void**)&WTh, g_WTh);   cudaGetSymbolAddress((void**)&WTl, g_WTl);
    cudaGetSymbolAddress((void**)&OwTh, g_OwTh); cudaGetSymbolAddress((void**)&OwTl, g_OwTl);
    cudaGetSymbolAddress((void**)&RwTh, g_RwTh); cudaGetSymbolAddress((void**)&RwTl, g_RwTl);
    cudaGetSymbolAddress((void**)&peh, g_peh);   cudaGetSymbolAddress((void**)&pel, g_pel);
    cudaGetSymbolAddress((void**)&rKh, g_rKh);   cudaGetSymbolAddress((void**)&rKl, g_rKl);
    cudaGetSymbolAddress((void**)&Qh, g_Qh);     cudaGetSymbolAddress((void**)&Ql, g_Ql);
    cudaGetSymbolAddress((void**)&Kh, g_Kh);     cudaGetSymbolAddress((void**)&Kl, g_Kl);
    cudaGetSymbolAddress((void**)&Vth, g_Vth);   cudaGetSymbolAddress((void**)&Vtl, g_Vtl);
    cudaGetSymbolAddress((void**)&sbd, g_sbd);
    cudaGetSymbolAddress((void**)&ath, g_ah);    cudaGetSymbolAddress((void**)&atl, g_al);

    cudaFuncSetAttribute(fused_attn, cudaFuncAttributeMaxDynamicSharedMemorySize, FA_SMEM);

    // launch 0: all conversions + weight packing + positional features
    prep_kernel<<<6600, 256>>>(x, Qw, Kw, Vw, outw, relKw,
                               xh, xl, WTh, WTl, OwTh, OwTl, RwTh, RwTl, peh, pel);

    // launch 1: rK = pe @ relKw
    hgemm<64><<<dim3(8, 24), 256>>>(peh, pel, 96, RwTh, RwTl, 96,
                                    rKh, rKl, 512, NPOS, 96);

    // launch 2: merged Q/K/V projection (+ V transpose epilogue + sbd blocks)
    qkv_gemm<<<dim3(15, 48), 256>>>(xh, xl, WTh, WTl, Qh, Ql, Kh, Kl,
                                    Vth, Vtl, rwb, rKh, rKl, rrb, sbd);

    // launch 3: fused attention (i-tile 64, single-buffered, 2 CTAs/SM)
    fused_attn<<<dim3(24, 32), 256, FA_SMEM>>>(Qh, Ql, Kh, Kl, rKh, rKl,
                                               Vth, Vtl, sbd, ath, atl);

    // launch 4: out = attn @ outw + outb
    out_gemm<<<dim3(6, 48), 256>>>(ath, atl, OwTh, OwTl, (float*)d_out, outb);
}

// round 15
// speedup vs baseline: 1.5078x; 1.5078x over previous
#include <cuda_runtime.h>
#include <cuda_bf16.h>
#include <math.h>

#define BB 4
#define LL 1536
#define DD 768
#define HH 8
#define NPOS 3071   // 2L-1

typedef __nv_bfloat16 bf16;

// ---------------- scratch (static device globals; no allocation) ----------------
__device__ bf16 g_xh[(size_t)BB * LL * DD],      g_xl[(size_t)BB * LL * DD];
__device__ bf16 g_WTh[1792 * 768],               g_WTl[1792 * 768];   // [Qw|Kw|Vw] transposed
__device__ bf16 g_OwTh[768 * 768],               g_OwTl[768 * 768];
__device__ bf16 g_RwTh[512 * 96],                g_RwTl[512 * 96];
__device__ bf16 g_peh[(size_t)NPOS * 96],        g_pel[(size_t)NPOS * 96];
// rK padded; pad rows stay zero
__device__ bf16 g_rKh[(size_t)3136 * 512],       g_rKl[(size_t)3136 * 512];
__device__ bf16 g_Qh[(size_t)BB * LL * 512],     g_Ql[(size_t)BB * LL * 512];   // Q*0.125 + rwb
__device__ bf16 g_Kh[(size_t)BB * LL * 512],     g_Kl[(size_t)BB * LL * 512];
__device__ bf16 g_Vth[(size_t)32 * 96 * LL],     g_Vtl[(size_t)32 * 96 * LL];   // V^T per (b,h)
__device__ float g_sbd[8 * NPOS];                                              // delta . rK
__device__ bf16 g_ah[(size_t)BB * LL * 768],     g_al[(size_t)BB * LL * 768];   // attn

// ---------------- small helpers ----------------
__device__ __forceinline__ unsigned smaddr(const void* p) {
    return (unsigned)__cvta_generic_to_shared(p);
}
__device__ __forceinline__ void ldsmx4(unsigned* r, unsigned a) {
    asm volatile("ldmatrix.sync.aligned.m8n8.x4.shared.b16 {%0,%1,%2,%3},[%4];\n"
        : "=r"(r[0]), "=r"(r[1]), "=r"(r[2]), "=r"(r[3]) : "r"(a));
}
__device__ __forceinline__ void ldsmx2(unsigned* r, unsigned a) {
    asm volatile("ldmatrix.sync.aligned.m8n8.x2.shared.b16 {%0,%1},[%2];\n"
        : "=r"(r[0]), "=r"(r[1]) : "r"(a));
}
__device__ __forceinline__ void mma16816(float* c, const unsigned* a, const unsigned* b) {
    asm volatile("mma.sync.aligned.m16n8k16.row.col.f32.bf16.bf16.f32 "
        "{%0,%1,%2,%3},{%4,%5,%6,%7},{%8,%9},{%0,%1,%2,%3};\n"
        : "+f"(c[0]), "+f"(c[1]), "+f"(c[2]), "+f"(c[3])
        : "r"(a[0]), "r"(a[1]), "r"(a[2]), "r"(a[3]), "r"(b[0]), "r"(b[1]));
}
__device__ __forceinline__ void f2split(float v, bf16& h, bf16& l) {
    h = __float2bfloat16(v);
    l = __float2bfloat16(v - __bfloat162float(h));
}
__device__ __forceinline__ unsigned packbf(float x, float y) {
    __nv_bfloat162 t;
    t.x = __float2bfloat16(x);
    t.y = __float2bfloat16(y);
    return *(unsigned*)&t;
}
__device__ __forceinline__ float bfhi(float x) {
    return __bfloat162float(__float2bfloat16(x));
}
// B-fragment pair loader: one ldmatrix.x4 delivers two n8k16 B fragments
// (rows row0..row0+16 of a [n][k] tile with pitch 72, k-cols kb..kb+16).
// r[0..1] = fragment rows row0..+8; r[2..3] = fragment rows row0+8..+16.
__device__ __forceinline__ void ldsmB4(unsigned* r, const bf16* base, int row0, int kb, int lane) {
    int j = lane >> 3;
    int row = row0 + (j >> 1) * 8 + (lane & 7);
    int col = kb + (j & 1) * 8;
    ldsmx4(r, smaddr(base + row * 72 + col));
}
#define CPA16(dst, src) asm volatile("cp.async.cg.shared.global [%0], [%1], 16;\n" \
    :: "r"(dst), "l"(src))
#define CPA_COMMIT() asm volatile("cp.async.commit_group;\n")
#define CPA_WAIT0()  asm volatile("cp.async.wait_group 0;\n")

// ---------------- positional features ----------------
__device__ __forceinline__ float gamma_pdf(float x, float cm1, float rate, float lognorm) {
    if (x <= 0.0f) return 0.0f;
    return expf(cm1 * logf(x) - rate * x - lognorm);
}

__device__ void pe_body(bf16* __restrict__ peh, bf16* __restrict__ pel, int idx) {
    if (idx >= NPOS) return;
    float p = (float)(idx - (LL - 1));
    float ap = fabsf(p);
    float sg = (p > 0.f) ? 1.f : ((p < 0.f) ? -1.f : 0.f);
    float max_range = log2f((float)LL);
    size_t base = (size_t)idx * 96;
    #pragma unroll 1
    for (int i = 0; i < 16; i++) {
        float hl = exp2f(3.0f + (max_range - 3.0f) * (float)i * (1.0f / 15.0f));
        float fe = exp2f(-ap / hl);
        float cw = exp2f((float)(i + 1)) - 1.0f;
        float fc = (cw > ap) ? 1.0f : 0.0f;
        float k1 = (float)(i + 1);
        float conc = 4.0f * k1 * k1;
        float rate = k1 * (1.0f / 24.0f);
        float lognorm = lgammaf(conc) - conc * logf(rate);
        float cm1 = conc - 1.0f;
        float mode = cm1 / rate;
        float t0 = fminf(fmaxf(floorf(mode), 0.0f), (float)(LL - 1));
        float t1 = fminf(t0 + 1.0f, (float)(LL - 1));
        float mx = fmaxf(gamma_pdf(t0, cm1, rate, lognorm),
                         gamma_pdf(t1, cm1, rate, lognorm)) + 1e-8f;
        float fg = (gamma_pdf(ap, cm1, rate, lognorm) + 1e-8f) / mx;
        float vals[6] = {fe, fc, fg, sg * fe, sg * fc, sg * fg};
        #pragma unroll
        for (int s = 0; s < 6; s++) {
            bf16 h, l; f2split(vals[s], h, l);
            peh[base + s * 16 + i] = h; pel[base + s * 16 + i] = l;
        }
    }
}

__device__ void tconv_body(const float* __restrict__ in, bf16* __restrict__ oh,
                           bf16* __restrict__ ol, int R, int Cn,
                           int bx, int by, int tid, float* ts) {
    int c0 = bx * 32, r0 = by * 32;
    int tx = tid & 31, ty = tid >> 5;
    #pragma unroll
    for (int t = 0; t < 4; t++)
        ts[(ty + t * 8) * 33 + tx] = in[(size_t)(r0 + ty + t * 8) * Cn + c0 + tx];
    __syncthreads();
    #pragma unroll
    for (int t = 0; t < 4; t++) {
        float v = ts[tx * 33 + ty + t * 8];
        size_t o = (size_t)(c0 + ty + t * 8) * R + r0 + tx;
        bf16 h, l; f2split(v, h, l);
        oh[o] = h; ol[o] = l;
    }
}

// ---------------- prep: convx + all weight transposes + pe, one launch ----------------
__global__ __launch_bounds__(256) void prep_kernel(
    const float* __restrict__ x, const float* __restrict__ Qw,
    const float* __restrict__ Kw, const float* __restrict__ Vw,
    const float* __restrict__ outw, const float* __restrict__ relKw,
    bf16* __restrict__ xh, bf16* __restrict__ xl,
    bf16* __restrict__ WTh, bf16* __restrict__ WTl,
    bf16* __restrict__ OwTh, bf16* __restrict__ OwTl,
    bf16* __restrict__ RwTh, bf16* __restrict__ RwTl,
    bf16* __restrict__ peh, bf16* __restrict__ pel)
{
    __shared__ float ts[32 * 33];
    int b0 = blockIdx.x, tid = threadIdx.x;
    if (b0 < 4608) {
        int idx4 = b0 * 256 + tid;
        float4 v = ((const float4*)x)[idx4];
        bf16 h0, l0, h1, l1, h2, l2, h3, l3;
        f2split(v.x, h0, l0); f2split(v.y, h1, l1);
        f2split(v.z, h2, l2); f2split(v.w, h3, l3);
        __nv_bfloat162 hh0; hh0.x = h0; hh0.y = h1;
        __nv_bfloat162 hh1; hh1.x = h2; hh1.y = h3;
        __nv_bfloat162 ll0; ll0.x = l0; ll0.y = l1;
        __nv_bfloat162 ll1; ll1.x = l2; ll1.y = l3;
        ((__nv_bfloat162*)xh)[idx4 * 2]     = hh0;
        ((__nv_bfloat162*)xh)[idx4 * 2 + 1] = hh1;
        ((__nv_bfloat162*)xl)[idx4 * 2]     = ll0;
        ((__nv_bfloat162*)xl)[idx4 * 2 + 1] = ll1;
    } else if (b0 < 4992) {
        int l = b0 - 4608;
        tconv_body(Qw, WTh, WTl, 768, 512, l % 16, l / 16, tid, ts);
    } else if (b0 < 5376) {
        int l = b0 - 4992;
        tconv_body(Kw, WTh + (size_t)512 * 768, WTl + (size_t)512 * 768,
                   768, 512, l % 16, l / 16, tid, ts);
    } else if (b0 < 5952) {
        int l = b0 - 5376;
        tconv_body(Vw, WTh + (size_t)1024 * 768, WTl + (size_t)1024 * 768,
                   768, 768, l % 24, l / 24, tid, ts);
    } else if (b0 < 6528) {
        int l = b0 - 5952;
        tconv_body(outw, OwTh, OwTl, 768, 768, l % 24, l / 24, tid, ts);
    } else if (b0 < 6576) {
        int l = b0 - 6528;
        tconv_body(relKw, RwTh, RwTl, 96, 512, l % 16, l / 16, tid, ts);
    } else {
        pe_body(peh, pel, (b0 - 6576) * 256 + tid);
    }
}

// ---------------- old-style split-bf16 GEMM (used for rK only) ----------------
template<int BN>
__global__ __launch_bounds__(256) void hgemm(
    const bf16* __restrict__ Ah, const bf16* __restrict__ Al, int lda,
    const bf16* __restrict__ Bh, const bf16* __restrict__ Bl, int ldb,
    bf16* __restrict__ Ch, bf16* __restrict__ Cl, int ldc,
    int M, int K)
{
    constexpr int PAD = 40;
    constexpr int NT = BN / 16;
    __shared__ __align__(16) bf16 sAh[128 * PAD], sAl[128 * PAD];
    __shared__ __align__(16) bf16 sBh[BN * PAD],  sBl[BN * PAD];

    int i0 = blockIdx.y * 128, j0 = blockIdx.x * BN;
    int tid = threadIdx.x, warp = tid >> 5, lane = tid & 31;
    int wm = warp >> 1, wn = warp & 1;
    int m0 = wm * 32, n0 = wn * (BN / 2);

    float acc[2][NT][4] = {};

    for (int kk = 0; kk < K; kk += 32) {
        uint4 avh[2], avl[2], bvh, bvl;
        #pragma unroll
        for (int t = 0; t < 2; t++) {
            int idx = tid + t * 256;
            int row = idx >> 2, c16 = idx & 3;
            int gr = i0 + row;
            if (gr < M) {
                avh[t] = *(const uint4*)(Ah + (size_t)gr * lda + kk + c16 * 8);
                avl[t] = *(const uint4*)(Al + (size_t)gr * lda + kk + c16 * 8);
            } else {
                avh[t] = make_uint4(0, 0, 0, 0); avl[t] = make_uint4(0, 0, 0, 0);
            }
        }
        {
            int row = tid >> 2, c16 = tid & 3;
            bvh = *(const uint4*)(Bh + (size_t)(j0 + row) * ldb + kk + c16 * 8);
            bvl = *(const uint4*)(Bl + (size_t)(j0 + row) * ldb + kk + c16 * 8);
        }
        __syncthreads();
        #pragma unroll
        for (int t = 0; t < 2; t++) {
            int idx = tid + t * 256;
            int row = idx >> 2, c16 = idx & 3;
            *(uint4*)(sAh + row * PAD + c16 * 8) = avh[t];
            *(uint4*)(sAl + row * PAD + c16 * 8) = avl[t];
        }
        {
            int row = tid >> 2, c16 = tid & 3;
            *(uint4*)(sBh + row * PAD + c16 * 8) = bvh;
            *(uint4*)(sBl + row * PAD + c16 * 8) = bvl;
        }
        __syncthreads();
        #pragma unroll
        for (int ks = 0; ks < 2; ks++) {
            int kb = ks * 16;
            unsigned ah[2][4], al[2][4], bh[NT][2], bl[NT][2];
            #pragma unroll
            for (int mt = 0; mt < 2; mt++) {
                int arow = m0 + mt * 16 + (lane & 15);
                int acol = kb + (lane >> 4) * 8;
                ldsmx4(ah[mt], smaddr(sAh + arow * PAD + acol));
                ldsmx4(al[mt], smaddr(sAl + arow * PAD + acol));
            }
            #pragma unroll
            for (int nt = 0; nt < NT; nt++) {
                int brow = n0 + nt * 8 + (lane & 7);
                int bcol = kb + ((lane >> 3) & 1) * 8;
                ldsmx2(bh[nt], smaddr(sBh + brow * PAD + bcol));
                ldsmx2(bl[nt], smaddr(sBl + brow * PAD + bcol));
            }
            #pragma unroll
            for (int mt = 0; mt < 2; mt++)
                #pragma unroll
                for (int nt = 0; nt < NT; nt++) {
                    mma16816(acc[mt][nt], ah[mt], bh[nt]);
                    mma16816(acc[mt][nt], ah[mt], bl[nt]);
                    mma16816(acc[mt][nt], al[mt], bh[nt]);
                }
        }
        __syncthreads();
    }

    #pragma unroll
    for (int mt = 0; mt < 2; mt++)
        #pragma unroll
        for (int nt = 0; nt < NT; nt++) {
            int r0 = i0 + m0 + mt * 16 + (lane >> 2);
            int jn = j0 + n0 + nt * 8 + ((lane & 3) << 1);
            float v00 = acc[mt][nt][0], v01 = acc[mt][nt][1];
            float v10 = acc[mt][nt][2], v11 = acc[mt][nt][3];
            bf16 h0, l0, h1, l1;
            if (r0 < M) {
                f2split(v00, h0, l0); f2split(v01, h1, l1);
                __nv_bfloat162 hh; hh.x = h0; hh.y = h1;
                __nv_bfloat162 ll; ll.x = l0; ll.y = l1;
                *(__nv_bfloat162*)(Ch + (size_t)r0 * ldc + jn) = hh;
                *(__nv_bfloat162*)(Cl + (size_t)r0 * ldc + jn) = ll;
            }
            if (r0 + 8 < M) {
                f2split(v10, h0, l0); f2split(v11, h1, l1);
                __nv_bfloat162 hh; hh.x = h0; hh.y = h1;
                __nv_bfloat162 ll; ll.x = l0; ll.y = l1;
                *(__nv_bfloat162*)(Ch + (size_t)(r0 + 8) * ldc + jn) = hh;
                *(__nv_bfloat162*)(Cl + (size_t)(r0 + 8) * ldc + jn) = ll;
            }
        }
}

// ======= improved 128x128 GEMM core: warp tile 64x32 =======
struct G128Acc { float a[4][4][4]; };

__device__ __forceinline__ void gemm128_core(
    const bf16* __restrict__ Ah, const bf16* __restrict__ Al, int lda,
    const bf16* __restrict__ Bh, const bf16* __restrict__ Bl, int ldb,
    int i0, int j0, int K, G128Acc& A_,
    bf16* sAh, bf16* sAl, bf16* sBh, bf16* sBl)
{
    constexpr int PAD = 40;
    int tid = threadIdx.x, warp = tid >> 5, lane = tid & 31;
    int m0 = (warp >> 2) * 64, n0 = (warp & 3) * 32;

    for (int kk = 0; kk < K; kk += 32) {
        uint4 avh[2], avl[2], bvh[2], bvl[2];
        #pragma unroll
        for (int t = 0; t < 2; t++) {
            int idx = tid + t * 256;
            int row = idx >> 2, c16 = idx & 3;
            avh[t] = *(const uint4*)(Ah + (size_t)(i0 + row) * lda + kk + c16 * 8);
            avl[t] = *(const uint4*)(Al + (size_t)(i0 + row) * lda + kk + c16 * 8);
            bvh[t] = *(const uint4*)(Bh + (size_t)(j0 + row) * ldb + kk + c16 * 8);
            bvl[t] = *(const uint4*)(Bl + (size_t)(j0 + row) * ldb + kk + c16 * 8);
        }
        __syncthreads();
        #pragma unroll
        for (int t = 0; t < 2; t++) {
            int idx = tid + t * 256;
            int row = idx >> 2, c16 = idx & 3;
            *(uint4*)(sAh + row * PAD + c16 * 8) = avh[t];
            *(uint4*)(sAl + row * PAD + c16 * 8) = avl[t];
            *(uint4*)(sBh + row * PAD + c16 * 8) = bvh[t];
            *(uint4*)(sBl + row * PAD + c16 * 8) = bvl[t];
        }
        __syncthreads();
        #pragma unroll
        for (int ks = 0; ks < 2; ks++) {
            int kb = ks * 16;
            unsigned ah[4][4], al[4][4], bh[4][2], bl[4][2];
            #pragma unroll
            for (int mt = 0; mt < 4; mt++) {
                int arow = m0 + mt * 16 + (lane & 15);
                int acol = kb + (lane >> 4) * 8;
                ldsmx4(ah[mt], smaddr(sAh + arow * PAD + acol));
                ldsmx4(al[mt], smaddr(sAl + arow * PAD + acol));
            }
            #pragma unroll
            for (int nt = 0; nt < 4; nt++) {
                int brow = n0 + nt * 8 + (lane & 7);
                int bcol = kb + ((lane >> 3) & 1) * 8;
                ldsmx2(bh[nt], smaddr(sBh + brow * PAD + bcol));
                ldsmx2(bl[nt], smaddr(sBl + brow * PAD + bcol));
            }
            #pragma unroll
            for (int mt = 0; mt < 4; mt++)
                #pragma unroll
                for (int nt = 0; nt < 4; nt++) {
                    mma16816(A_.a[mt][nt], ah[mt], bh[nt]);
                    mma16816(A_.a[mt][nt], ah[mt], bl[nt]);
                    mma16816(A_.a[mt][nt], al[mt], bh[nt]);
                }
        }
        __syncthreads();
    }
}

// ---------------- out projection: fp32 out + bias ----------------
__global__ __launch_bounds__(256) void out_gemm(
    const bf16* __restrict__ Ah, const bf16* __restrict__ Al,
    const bf16* __restrict__ Bh, const bf16* __restrict__ Bl,
    float* __restrict__ Cf, const float* __restrict__ bias)
{
    constexpr int PAD = 40;
    __shared__ __align__(16) bf16 sAh[128 * PAD], sAl[128 * PAD];
    __shared__ __align__(16) bf16 sBh[128 * PAD], sBl[128 * PAD];
    int i0 = blockIdx.y * 128, j0 = blockIdx.x * 128;
    int warp = threadIdx.x >> 5, lane = threadIdx.x & 31;
    int m0 = (warp >> 2) * 64, n0 = (warp & 3) * 32;

    G128Acc acc;
    #pragma unroll
    for (int mt = 0; mt < 4; mt++)
        #pragma unroll
        for (int nt = 0; nt < 4; nt++)
            #pragma unroll
            for (int e = 0; e < 4; e++) acc.a[mt][nt][e] = 0.0f;

    gemm128_core(Ah, Al, 768, Bh, Bl, 768, i0, j0, 768, acc, sAh, sAl, sBh, sBl);

    #pragma unroll
    for (int mt = 0; mt < 4; mt++)
        #pragma unroll
        for (int nt = 0; nt < 4; nt++) {
            int r0 = i0 + m0 + mt * 16 + (lane >> 2);
            int jn = j0 + n0 + nt * 8 + ((lane & 3) << 1);
            float b0 = bias[jn], b1 = bias[jn + 1];
            *(float2*)(Cf + (size_t)r0 * 768 + jn) =
                make_float2(acc.a[mt][nt][0] + b0, acc.a[mt][nt][1] + b1);
            *(float2*)(Cf + (size_t)(r0 + 8) * 768 + jn) =
                make_float2(acc.a[mt][nt][2] + b0, acc.a[mt][nt][3] + b1);
        }
}

// ---------------- merged QKV projection + V-transpose epilogue + sbd blocks ----------------
__global__ __launch_bounds__(256) void qkv_gemm(
    const bf16* __restrict__ Ah, const bf16* __restrict__ Al,
    const bf16* __restrict__ Bh, const bf16* __restrict__ Bl,
    bf16* __restrict__ Qh, bf16* __restrict__ Ql,
    bf16* __restrict__ Kh, bf16* __restrict__ Kl,
    bf16* __restrict__ Vth, bf16* __restrict__ Vtl,
    const float* __restrict__ rwb,
    const bf16* __restrict__ Rh, const bf16* __restrict__ Rl,
    const float* __restrict__ rrb, float* __restrict__ sbd)
{
    constexpr int PAD = 40;
    __shared__ __align__(16) bf16 sAh[128 * PAD], sAl[128 * PAD];
    __shared__ __align__(16) bf16 sBh[128 * PAD], sBl[128 * PAD];
    int tid = threadIdx.x;

    if (blockIdx.x == 14) {
        int idx0 = blockIdx.y * 256 + tid;
        #pragma unroll
        for (int rep = 0; rep < 2; rep++) {
            int idx = idx0 + rep * 12288;
            if (idx < 8 * NPOS) {
                int h = idx / NPOS, p = idx % NPOS;
                float s = 0.0f;
                #pragma unroll 8
                for (int d = 0; d < 64; d++) {
                    size_t o = (size_t)p * 512 + h * 64 + d;
                    s += (rrb[h * 64 + d] - rwb[h * 64 + d]) *
                         (__bfloat162float(Rh[o]) + __bfloat162float(Rl[o]));
                }
                sbd[idx] = s;
            }
        }
        return;
    }

    int i0 = blockIdx.y * 128, j0 = blockIdx.x * 128;
    int warp = tid >> 5, lane = tid & 31;
    int m0 = (warp >> 2) * 64, n0 = (warp & 3) * 32;

    G128Acc acc;
    #pragma unroll
    for (int mt = 0; mt < 4; mt++)
        #pragma unroll
        for (int nt = 0; nt < 4; nt++)
            #pragma unroll
            for (int e = 0; e < 4; e++) acc.a[mt][nt][e] = 0.0f;

    gemm128_core(Ah, Al, 768, Bh, Bl, 768, i0, j0, 768, acc, sAh, sAl, sBh, sBl);

    int jt = blockIdx.x;
    if (jt < 8) {
        bf16 *Ch, *Cl; int jbase; float alpha; const float* bias;
        if (jt < 4) { Ch = Qh; Cl = Ql; jbase = jt * 128; alpha = 0.125f; bias = rwb; }
        else        { Ch = Kh; Cl = Kl; jbase = (jt - 4) * 128; alpha = 1.0f; bias = nullptr; }
        #pragma unroll
        for (int mt = 0; mt < 4; mt++)
            #pragma unroll
            for (int nt = 0; nt < 4; nt++) {
                int r0 = i0 + m0 + mt * 16 + (lane >> 2);
                int jn = jbase + n0 + nt * 8 + ((lane & 3) << 1);
                float b0 = bias ? bias[jn] : 0.0f;
                float b1 = bias ? bias[jn + 1] : 0.0f;
                float v00 = alpha * acc.a[mt][nt][0] + b0;
                float v01 = alpha * acc.a[mt][nt][1] + b1;
                float v10 = alpha * acc.a[mt][nt][2] + b0;
                float v11 = alpha * acc.a[mt][nt][3] + b1;
                bf16 h0, l0, h1, l1;
                f2split(v00, h0, l0); f2split(v01, h1, l1);
                __nv_bfloat162 hh; hh.x = h0; hh.y = h1;
                __nv_bfloat162 ll; ll.x = l0; ll.y = l1;
                *(__nv_bfloat162*)(Ch + (size_t)r0 * 512 + jn) = hh;
                *(__nv_bfloat162*)(Cl + (size_t)r0 * 512 + jn) = ll;
                f2split(v10, h0, l0); f2split(v11, h1, l1);
                hh.x = h0; hh.y = h1; ll.x = l0; ll.y = l1;
                *(__nv_bfloat162*)(Ch + (size_t)(r0 + 8) * 512 + jn) = hh;
                *(__nv_bfloat162*)(Cl + (size_t)(r0 + 8) * 512 + jn) = ll;
            }
    } else {
        #pragma unroll
        for (int mt = 0; mt < 4; mt++)
            #pragma unroll
            for (int nt = 0; nt < 4; nt++) {
                int r = i0 + m0 + mt * 16 + (lane >> 2);
                int cv = (jt - 8) * 128 + n0 + nt * 8 + ((lane & 3) << 1);
                int bb2 = r / LL;
                int ii = r - bb2 * LL;
                int h = cv / 96, dv = cv - h * 96;
                size_t zo = ((size_t)(bb2 * 8 + h)) * 96 * LL;
                bf16 h0, l0;
                f2split(acc.a[mt][nt][0], h0, l0);
                Vth[zo + (size_t)dv * LL + ii] = h0;
                Vtl[zo + (size_t)dv * LL + ii] = l0;
                f2split(acc.a[mt][nt][1], h0, l0);
                Vth[zo + (size_t)(dv + 1) * LL + ii] = h0;
                Vtl[zo + (size_t)(dv + 1) * LL + ii] = l0;
                f2split(acc.a[mt][nt][2], h0, l0);
                Vth[zo + (size_t)dv * LL + ii + 8] = h0;
                Vtl[zo + (size_t)dv * LL + ii + 8] = l0;
                f2split(acc.a[mt][nt][3], h0, l0);
                Vth[zo + (size_t)(dv + 1) * LL + ii + 8] = h0;
                Vtl[zo + (size_t)(dv + 1) * LL + ii + 8] = l0;
            }
    }
}

// ===== fused flash attention (R10 proven config: double-buffered, rolling band) =====
// + ldsmB4 pair loads (halved ldmatrix count in band/content/PV loops)
#define STG_SZ 64512
#define FA_SMEM 199680
__device__ __forceinline__ void fa_issue_stage(
    unsigned char* base, int tid,
    const bf16* Kh, const bf16* Kl, size_t qkbase, int j0,
    const bf16* Rh, const bf16* Rl, int bandrow0, int h,
    const bf16* Vth, const bf16* Vtl, size_t voff)
{
    bf16* sKh = (bf16*)(base);
    bf16* sKl = (bf16*)(base + 9216);
    bf16* sBh = (bf16*)(base + 18432);
    bf16* sBl = (bf16*)(base + 27648);
    bf16* sVh = (bf16*)(base + 36864);
    bf16* sVl = (bf16*)(base + 50688);
    #pragma unroll
    for (int t = 0; t < 4; t++) {
        int idx = tid + t * 256;
        int sp = idx >> 9;
        int r = (idx & 511) >> 3, c16 = idx & 7;
        CPA16(smaddr((sp ? sKl : sKh) + r * 72 + c16 * 8),
              (sp ? Kl : Kh) + qkbase + (size_t)(j0 + r) * 512 + c16 * 8);
        CPA16(smaddr((sp ? sBl : sBh) + r * 72 + c16 * 8),
              (sp ? Rl : Rh) + (size_t)(bandrow0 + r) * 512 + h * 64 + c16 * 8);
    }
    #pragma unroll
    for (int t = 0; t < 6; t++) {
        int idx = tid + t * 256;
        int sp = idx >= 768;
        int rem = idx - sp * 768;
        int r = rem >> 3, c16 = rem & 7;
        CPA16(smaddr((sp ? sVl : sVh) + r * 72 + c16 * 8),
              (sp ? Vtl : Vth) + voff + (size_t)r * LL + j0 + c16 * 8);
    }
}

// band mma over one 64-row rK segment -> bandS columns [phys*64, phys*64+64)
__device__ __forceinline__ void band_seg_mma(
    const bf16* sBh, const bf16* sBl, int phys,
    const unsigned aQh[4][4], const unsigned aQl[4][4],
    float* bandS, int wn, int lane, int rowA, int rowB, int c2)
{
    float bacc[4][4];
    #pragma unroll
    for (int n = 0; n < 4; n++)
        #pragma unroll
        for (int e = 0; e < 4; e++) bacc[n][e] = 0.0f;
    #pragma unroll
    for (int ks = 0; ks < 4; ks++) {
        #pragma unroll
        for (int p = 0; p < 2; p++) {
            unsigned bh4[4], bl4[4];
            ldsmB4(bh4, sBh, wn * 32 + p * 16, ks * 16, lane);
            ldsmB4(bl4, sBl, wn * 32 + p * 16, ks * 16, lane);
            mma16816(bacc[p * 2], aQh[ks], bh4);
            mma16816(bacc[p * 2], aQh[ks], bl4);
            mma16816(bacc[p * 2], aQl[ks], bh4);
            mma16816(bacc[p * 2 + 1], aQh[ks], bh4 + 2);
            mma16816(bacc[p * 2 + 1], aQh[ks], bl4 + 2);
            mma16816(bacc[p * 2 + 1], aQl[ks], bh4 + 2);
        }
    }
    #pragma unroll
    for (int nt = 0; nt < 4; nt++) {
        int col = phys * 64 + wn * 32 + nt * 8 + c2;
        bandS[rowA * 130 + col]     = bacc[nt][0];
        bandS[rowA * 130 + col + 1] = bacc[nt][1];
        bandS[rowB * 130 + col]     = bacc[nt][2];
        bandS[rowB * 130 + col + 1] = bacc[nt][3];
    }
}

__global__ __launch_bounds__(256) void fused_attn(
    const bf16* __restrict__ Qh, const bf16* __restrict__ Ql,
    const bf16* __restrict__ Kh, const bf16* __restrict__ Kl,
    const bf16* __restrict__ Rh, const bf16* __restrict__ Rl,
    const bf16* __restrict__ Vth, const bf16* __restrict__ Vtl,
    const float* __restrict__ sbd_g,
    bf16* __restrict__ Oh, bf16* __restrict__ Ol)
{
    extern __shared__ __align__(16) unsigned char smc[];
    bf16* sQh  = (bf16*)(smc + 129024);
    bf16* sQl  = (bf16*)(smc + 138240);
    bf16* sB0h = (bf16*)(smc + 147456);
    bf16* sB0l = (bf16*)(smc + 156672);
    float* bandS = (float*)(smc + 165888);
    float* sbdS  = (float*)(smc + 199168);

    int tid = threadIdx.x, warp = tid >> 5, lane = tid & 31;
    int wm = warp >> 1, wn = warp & 1;
    int m0 = wm * 16;
    int z = blockIdx.y, b = z >> 3, h = z & 7;
    int i0 = blockIdx.x * 64;
    size_t qkbase = ((size_t)b * LL) * 512 + h * 64;
    size_t voff = (size_t)z * 96 * LL;
    int bandbase = 1472 - i0;

    // --- prologue: Q tile, band seg-0 rows, stage 0 ---
    #pragma unroll
    for (int t = 0; t < 4; t++) {
        int idx = tid + t * 256;
        int sp = idx >> 9;
        int r = (idx & 511) >> 3, c16 = idx & 7;
        CPA16(smaddr(((sp ? sQl : sQh)) + r * 72 + c16 * 8),
              (sp ? Ql : Qh) + qkbase + (size_t)(i0 + r) * 512 + c16 * 8);
        CPA16(smaddr(((sp ? sB0l : sB0h)) + r * 72 + c16 * 8),
              (sp ? Rl : Rh) + (size_t)(bandbase + r) * 512 + h * 64 + c16 * 8);
    }
    fa_issue_stage(smc, tid, Kh, Kl, qkbase, 0, Rh, Rl, bandbase + 64, h, Vth, Vtl, voff);
    CPA_COMMIT();

    float mA = -1e30f, mB = -1e30f, lA = 0.0f, lB = 0.0f;
    float acc[12][4];
    #pragma unroll
    for (int n = 0; n < 12; n++)
        #pragma unroll
        for (int e = 0; e < 4; e++) acc[n][e] = 0.0f;

    unsigned aQh[4][4], aQl[4][4];
    int r4 = lane >> 2, c2 = (lane & 3) << 1;
    int rowA = m0 + r4, rowB = m0 + r4 + 8;

    for (int jt = 0; jt < 24; jt++) {
        int j0 = jt * 64;
        int k0g = 1472 + j0 - i0;
        unsigned char* cbase = smc + (size_t)(jt & 1) * STG_SZ;
        bf16* sKh_c = (bf16*)(cbase);
        bf16* sKl_c = (bf16*)(cbase + 9216);
        bf16* sBh_c = (bf16*)(cbase + 18432);
        bf16* sBl_c = (bf16*)(cbase + 27648);
        bf16* sVh_c = (bf16*)(cbase + 36864);
        bf16* sVl_c = (bf16*)(cbase + 50688);

        float sbdv = (tid < 127) ? sbd_g[h * NPOS + k0g + tid] : 0.0f;

        CPA_WAIT0();
        __syncthreads();

        if (jt + 1 < 24) {
            fa_issue_stage(smc + (size_t)((jt + 1) & 1) * STG_SZ, tid,
                           Kh, Kl, qkbase, j0 + 64, Rh, Rl,
                           bandbase + 64 * (jt + 2), h, Vth, Vtl, voff);
            CPA_COMMIT();
        }

        if (jt == 0) {
            #pragma unroll
            for (int ks = 0; ks < 4; ks++) {
                int arow = m0 + (lane & 15);
                int acol = ks * 16 + (lane >> 4) * 8;
                ldsmx4(aQh[ks], smaddr(sQh + arow * 72 + acol));
                ldsmx4(aQl[ks], smaddr(sQl + arow * 72 + acol));
            }
            band_seg_mma(sB0h, sB0l, 0, aQh, aQl, bandS, wn, lane, rowA, rowB, c2);
        }
        band_seg_mma(sBh_c, sBl_c, (jt + 1) & 1, aQh, aQl, bandS, wn, lane, rowA, rowB, c2);
        if (tid < 128) sbdS[tid] = sbdv;

        // content mma with pair loads
        float cacc[4][4];
        #pragma unroll
        for (int n = 0; n < 4; n++)
            #pragma unroll
            for (int e = 0; e < 4; e++) cacc[n][e] = 0.0f;
        #pragma unroll
        for (int ks = 0; ks < 4; ks++) {
            #pragma unroll
            for (int p = 0; p < 2; p++) {
                unsigned kh4[4], kl4[4];
                ldsmB4(kh4, sKh_c, wn * 32 + p * 16, ks * 16, lane);
                ldsmB4(kl4, sKl_c, wn * 32 + p * 16, ks * 16, lane);
                mma16816(cacc[p * 2], aQh[ks], kh4);
                mma16816(cacc[p * 2], aQh[ks], kl4);
                mma16816(cacc[p * 2], aQl[ks], kh4);
                mma16816(cacc[p * 2 + 1], aQh[ks], kh4 + 2);
                mma16816(cacc[p * 2 + 1], aQh[ks], kl4 + 2);
                mma16816(cacc[p * 2 + 1], aQl[ks], kh4 + 2);
            }
        }
        __syncthreads();

        float rmA = -1e30f, rmB = -1e30f;
        #pragma unroll
        for (int nt = 0; nt < 4; nt++) {
            int jj0 = wn * 32 + nt * 8 + c2;
            #pragma unroll
            for (int u = 0; u < 2; u++) {
                int jj = jj0 + u;
                int pA = 63 + jj - rowA;
                int pB = 63 + jj - rowB;
                int iA = ((jt + (pA >> 6)) & 1) * 64 + (pA & 63);
                int iB = ((jt + (pB >> 6)) & 1) * 64 + (pB & 63);
                cacc[nt][u]     += bandS[rowA * 130 + iA] + sbdS[pA];
                cacc[nt][2 + u] += bandS[rowB * 130 + iB] + sbdS[pB];
                rmA = fmaxf(rmA, cacc[nt][u]);
                rmB = fmaxf(rmB, cacc[nt][2 + u]);
            }
        }
        rmA = fmaxf(rmA, __shfl_xor_sync(0xffffffffu, rmA, 1));
        rmA = fmaxf(rmA, __shfl_xor_sync(0xffffffffu, rmA, 2));
        rmB = fmaxf(rmB, __shfl_xor_sync(0xffffffffu, rmB, 1));
        rmB = fmaxf(rmB, __shfl_xor_sync(0xffffffffu, rmB, 2));

        float mnA = fmaxf(mA, rmA), mnB = fmaxf(mB, rmB);
        float alA = __expf(mA - mnA), alB = __expf(mB - mnB);
        mA = mnA; mB = mnB;

        float ssA = 0.0f, ssB = 0.0f;
        #pragma unroll
        for (int nt = 0; nt < 4; nt++) {
            cacc[nt][0] = __expf(cacc[nt][0] - mA);
            cacc[nt][1] = __expf(cacc[nt][1] - mA);
            cacc[nt][2] = __expf(cacc[nt][2] - mB);
            cacc[nt][3] = __expf(cacc[nt][3] - mB);
            ssA += cacc[nt][0] + cacc[nt][1];
            ssB += cacc[nt][2] + cacc[nt][3];
        }
        ssA += __shfl_xor_sync(0xffffffffu, ssA, 1);
        ssA += __shfl_xor_sync(0xffffffffu, ssA, 2);
        ssB += __shfl_xor_sync(0xffffffffu, ssB, 1);
        ssB += __shfl_xor_sync(0xffffffffu, ssB, 2);
        lA = lA * alA + ssA;
        lB = lB * alB + ssB;
        #pragma unroll
        for (int n = 0; n < 12; n++) {
            acc[n][0] *= alA; acc[n][1] *= alA;
            acc[n][2] *= alB; acc[n][3] *= alB;
        }

        // PV with pair loads: P (k = wn*32 + ks*16) x V
        #pragma unroll
        for (int ks = 0; ks < 2; ks++) {
            int n2 = ks * 2;
            unsigned aPh[4], aPl[4];
            aPh[0] = packbf(cacc[n2][0], cacc[n2][1]);
            aPh[1] = packbf(cacc[n2][2], cacc[n2][3]);
            aPh[2] = packbf(cacc[n2 + 1][0], cacc[n2 + 1][1]);
            aPh[3] = packbf(cacc[n2 + 1][2], cacc[n2 + 1][3]);
            aPl[0] = packbf(cacc[n2][0] - bfhi(cacc[n2][0]), cacc[n2][1] - bfhi(cacc[n2][1]));
            aPl[1] = packbf(cacc[n2][2] - bfhi(cacc[n2][2]), cacc[n2][3] - bfhi(cacc[n2][3]));
            aPl[2] = packbf(cacc[n2 + 1][0] - bfhi(cacc[n2 + 1][0]), cacc[n2 + 1][1] - bfhi(cacc[n2 + 1][1]));
            aPl[3] = packbf(cacc[n2 + 1][2] - bfhi(cacc[n2 + 1][2]), cacc[n2 + 1][3] - bfhi(cacc[n2 + 1][3]));
            int vcol = wn * 32 + ks * 16;
            #pragma unroll
            for (int pp = 0; pp < 6; pp++) {
                unsigned vh4[4], vl4[4];
                ldsmB4(vh4, sVh_c, pp * 16, vcol, lane);
                ldsmB4(vl4, sVl_c, pp * 16, vcol, lane);
                mma16816(acc[2 * pp], aPh, vh4);
                mma16816(acc[2 * pp], aPh, vl4);
                mma16816(acc[2 * pp], aPl, vh4);
                mma16816(acc[2 * pp + 1], aPh, vh4 + 2);
                mma16816(acc[2 * pp + 1], aPh, vl4 + 2);
                mma16816(acc[2 * pp + 1], aPl, vh4 + 2);
            }
        }
    }

    // --- epilogue: merge the two wn halves, divide, write split bf16 ---
    __syncthreads();
    float* exch = bandS;
    float* mS = bandS + 6144;
    float* lS = bandS + 6208;
    if (wn == 1) {
        #pragma unroll
        for (int nt = 0; nt < 12; nt++) {
            int col = nt * 8 + c2;
            exch[rowA * 96 + col]     = acc[nt][0];
            exch[rowA * 96 + col + 1] = acc[nt][1];
            exch[rowB * 96 + col]     = acc[nt][2];
            exch[rowB * 96 + col + 1] = acc[nt][3];
        }
        if ((lane & 3) == 0) {
            mS[rowA] = mA; lS[rowA] = lA;
            mS[rowB] = mB; lS[rowB] = lB;
        }
    }
    __syncthreads();
    if (wn == 0) {
        float m1A = mS[rowA], l1A = lS[rowA];
        float m1B = mS[rowB], l1B = lS[rowB];
        float mMA = fmaxf(mA, m1A), mMB = fmaxf(mB, m1B);
        float c0A = __expf(mA - mMA), c1A = __expf(m1A - mMA);
        float c0B = __expf(mB - mMB), c1B = __expf(m1B - mMB);
        float invA = 1.0f / (c0A * lA + c1A * l1A);
        float invB = 1.0f / (c0B * lB + c1B * l1B);
        size_t obase = ((size_t)(b * LL + i0)) * 768 + h * 96;
        #pragma unroll
        for (int nt = 0; nt < 12; nt++) {
            int col = nt * 8 + c2;
            float d0 = (c0A * acc[nt][0] + c1A * exch[rowA * 96 + col]) * invA;
            float d1 = (c0A * acc[nt][1] + c1A * exch[rowA * 96 + col + 1]) * invA;
            float d2 = (c0B * acc[nt][2] + c1B * exch[rowB * 96 + col]) * invB;
            float d3 = (c0B * acc[nt][3] + c1B * exch[rowB * 96 + col + 1]) * invB;
            bf16 h0, l0, h1, l1;
            f2split(d0, h0, l0); f2split(d1, h1, l1);
            __nv_bfloat162 hh; hh.x = h0; hh.y = h1;
            __nv_bfloat162 ll; ll.x = l0; ll.y = l1;
            *(__nv_bfloat162*)(Oh + obase + (size_t)rowA * 768 + col) = hh;
            *(__nv_bfloat162*)(Ol + obase + (size_t)rowA * 768 + col) = ll;
            f2split(d2, h0, l0); f2split(d3, h1, l1);
            hh.x = h0; hh.y = h1; ll.x = l0; ll.y = l1;
            *(__nv_bfloat162*)(Oh + obase + (size_t)rowB * 768 + col) = hh;
            *(__nv_bfloat162*)(Ol + obase + (size_t)rowB * 768 + col) = ll;
        }
    }
}

// ---------------- launch ----------------
extern "C" void kernel_launch(void* const* d_in, const int* in_sizes, int n_in,
                              void* d_out, int out_size) {
    (void)in_sizes; (void)n_in; (void)out_size;
    const float* x     = (const float*)d_in[0];
    const float* Qw    = (const float*)d_in[1];
    const float* Kw    = (const float*)d_in[2];
    const float* Vw    = (const float*)d_in[3];
    const float* outw  = (const float*)d_in[4];
    const float* outb  = (const float*)d_in[5];
    const float* relKw = (const float*)d_in[6];
    const float* rwb   = (const float*)d_in[7];
    const float* rrb   = (const float*)d_in[8];

    bf16 *xh, *xl, *WTh, *WTl, *OwTh, *OwTl, *RwTh, *RwTl;
    bf16 *peh, *pel, *rKh, *rKl, *Qh, *Ql, *Kh, *Kl, *Vth, *Vtl, *ath, *atl;
    float *sbd;
    cudaGetSymbolAddress((void**)&xh, g_xh);     cudaGetSymbolAddress((void**)&xl, g_xl);
    cudaGetSymbolAddress((void**)&WTh, g_WTh);   cudaGetSymbolAddress((void**)&WTl, g_WTl);
    cudaGetSymbolAddress((void**)&OwTh, g_OwTh); cudaGetSymbolAddress((void**)&OwTl, g_OwTl);
    cudaGetSymbolAddress((void**)&RwTh, g_RwTh); cudaGetSymbolAddress((void**)&RwTl, g_RwTl);
    cudaGetSymbolAddress((void**)&peh, g_peh);   cudaGetSymbolAddress((void**)&pel, g_pel);
    cudaGetSymbolAddress((void**)&rKh, g_rKh);   cudaGetSymbolAddress((void**)&rKl, g_rKl);
    cudaGetSymbolAddress((void**)&Qh, g_Qh);     cudaGetSymbolAddress((void**)&Ql, g_Ql);
    cudaGetSymbolAddress((void**)&Kh, g_Kh);     cudaGetSymbolAddress((void**)&Kl, g_Kl);
    cudaGetSymbolAddress((void**)&Vth, g_Vth);   cudaGetSymbolAddress((void**)&Vtl, g_Vtl);
    cudaGetSymbolAddress((void**)&sbd, g_sbd);
    cudaGetSymbolAddress((void**)&ath, g_ah);    cudaGetSymbolAddress((void**)&atl, g_al);

    cudaFuncSetAttribute(fused_attn, cudaFuncAttributeMaxDynamicSharedMemorySize, FA_SMEM);

    // launch 0: all conversions + weight packing + positional features
    prep_kernel<<<6600, 256>>>(x, Qw, Kw, Vw, outw, relKw,
                               xh, xl, WTh, WTl, OwTh, OwTl, RwTh, RwTl, peh, pel);

    // launch 1: rK = pe @ relKw
    hgemm<64><<<dim3(8, 24), 256>>>(peh, pel, 96, RwTh, RwTl, 96,
                                    rKh, rKl, 512, NPOS, 96);

    // launch 2: merged Q/K/V projection (+ V transpose epilogue + sbd blocks)
    qkv_gemm<<<dim3(15, 48), 256>>>(xh, xl, WTh, WTl, Qh, Ql, Kh, Kl,
                                    Vth, Vtl, rwb, rKh, rKl, rrb, sbd);

    // launch 3: fused attention (R10 config + ldsmB4 pair loads)
    fused_attn<<<dim3(24, 32), 256, FA_SMEM>>>(Qh, Ql, Kh, Kl, rKh, rKl,
                                               Vth, Vtl, sbd, ath, atl);

    // launch 4: out = attn @ outw + outb
    out_gemm<<<dim3(6, 48), 256>>>(ath, atl, OwTh, OwTl, (float*)d_out, outb);
}